// round 8
// baseline (speedup 1.0000x reference)
#include <cuda_runtime.h>
#include <cuda_fp16.h>
#include <cstdint>

#define BM      16
#define THREADS 256
#define NWARP   8
#define EPS     0.10f
#define MAXCAND 256

__device__ uint2  g_bfrag[128 * 4 * 32];   // [ntg][kc][lane]{b0,b1} fp16 of -2e
__device__ float  g_wn1[1024];             // ||e_c||^2 + 1
__device__ double g_loss;

__device__ __forceinline__ float rcpf(float x) {
    float r; asm("rcp.approx.f32 %0, %1;" : "=f"(r) : "f"(x)); return r;
}
__device__ __forceinline__ unsigned int ordered_u32(float f) {
    unsigned int u = __float_as_uint(f);
    return (u & 0x80000000u) ? ~u : (u | 0x80000000u);
}
// fp16-accumulate MMA: D,C fp16 (2 regs), 2x rate vs f32-acc on legacy pipe
__device__ __forceinline__ void mma_f16acc(uint32_t* c, const uint32_t* a,
                                           uint32_t b0, uint32_t b1) {
    asm volatile(
        "mma.sync.aligned.m16n8k16.row.col.f16.f16.f16.f16 "
        "{%0,%1}, {%2,%3,%4,%5}, {%6,%7}, {%0,%1};"
        : "+r"(c[0]), "+r"(c[1])
        : "r"(a[0]), "r"(a[1]), "r"(a[2]), "r"(a[3]), "r"(b0), "r"(b1));
}
__device__ __forceinline__ uint32_t h2pack(float a, float b) {
    __half2 h = __floats2half2_rn(a, b);
    return *(uint32_t*)&h;
}

// ---------------------------------------------------------------------------
// Prep: block ntg stages 8 codebook rows -> wn1 + fp16 B fragments (m16n8k16)
// ---------------------------------------------------------------------------
__global__ void vq_prep(const float* __restrict__ cb) {
    __shared__ float rows[8 * 64];
    const int tid = threadIdx.x;
    const int ntg = blockIdx.x;
    if (ntg == 0 && tid == 0) g_loss = 0.0;
    ((float2*)rows)[tid] = ((const float2*)(cb + (size_t)ntg * 512))[tid];
    __syncthreads();
    if (tid < 8) {
        float s = 0.f;
        const float* r = rows + tid * 64;
#pragma unroll 16
        for (int k = 0; k < 64; k++) { float v = r[k]; s += v * v; }
        g_wn1[ntg * 8 + tid] = s + 1.f;
    }
    if (tid < 128) {
        const int lane = tid & 31;
        const int kc   = tid >> 5;          // 0..3
        const int g = lane >> 2, tq = lane & 3;
        const int k0 = kc * 16 + tq * 2;
        const float* r = rows + g * 64;
        uint2 o;
        o.x = h2pack(-2.f * r[k0],     -2.f * r[k0 + 1]);
        o.y = h2pack(-2.f * r[k0 + 8], -2.f * r[k0 + 9]);
        g_bfrag[(size_t)ntg * 128 + tid] = o;
    }
}

// ---------------------------------------------------------------------------
// Main: 16 rows x 1024 cols/CTA, 8 warps x (16x128 slab), occ 2/SM, f16 acc
// ---------------------------------------------------------------------------
__global__ void __launch_bounds__(THREADS, 2)
vq_main(const float* __restrict__ z, const float* __restrict__ cb,
        float* __restrict__ q_out, float* __restrict__ zq_out) {
    __shared__ float z_s[16 * 64];
    __shared__ uint4 af_s[128];               // A frags [kc][lane]
    __shared__ float wn_s[1024];
    __shared__ float zn2_s[16];
    __shared__ float inv_s[16];
    __shared__ float thr_s[16];
    __shared__ int   bc_s[16];
    __shared__ float rs_p[NWARP][16];
    __shared__ float qm_p[NWARP][16];
    __shared__ unsigned long long rowbest[16];
    __shared__ unsigned int cand_s[MAXCAND];
    __shared__ int ncand_s;

    const int tid  = threadIdx.x;
    const int wid  = tid >> 5;
    const int lane = tid & 31;
    const int g    = lane >> 2;
    const int tq   = lane & 3;
    const int r0   = blockIdx.x * BM;

    ((float4*)z_s)[tid] = ((const float4*)(z + (size_t)r0 * 64))[tid];
    ((float4*)wn_s)[tid] = ((const float4*)g_wn1)[tid];
    __syncthreads();

    // A fragments fp16: slot = kc*32 + lane
    if (tid < 128) {
        int kc = tid >> 5, ln = tid & 31;
        int gg = ln >> 2, qq = ln & 3;
        int k0 = kc * 16 + qq * 2;
        const float* zr0 = z_s + gg * 64;
        const float* zr1 = z_s + (gg + 8) * 64;
        uint4 v;
        v.x = h2pack(zr0[k0],     zr0[k0 + 1]);
        v.y = h2pack(zr1[k0],     zr1[k0 + 1]);
        v.z = h2pack(zr0[k0 + 8], zr0[k0 + 9]);
        v.w = h2pack(zr1[k0 + 8], zr1[k0 + 9]);
        af_s[tid] = v;
    }
    if (tid < 16) {
        float s = 0.f;
        const float* zr = z_s + tid * 64;
#pragma unroll 16
        for (int k = 0; k < 64; k++) { float v = zr[k]; s += v * v; }
        zn2_s[tid] = s;
        rowbest[tid] = 0ull;
    }
    if (tid == 0) ncand_s = 0;
    __syncthreads();

    // ---- GEMM (f16 acc): warp wid owns cols wid*128..+127; 64 MMAs/warp ----
    uint32_t acc[16][2];
#pragma unroll
    for (int nt = 0; nt < 16; nt++) { acc[nt][0] = 0u; acc[nt][1] = 0u; }

    const uint2* bb = g_bfrag + (size_t)(wid * 16) * 128 + lane;

#pragma unroll
    for (int half = 0; half < 2; half++) {
        uint2 bf[8];
#pragma unroll
        for (int j = 0; j < 8; j++) bf[j] = __ldg(bb + (half * 8 + j) * 128);
#pragma unroll
        for (int kc = 0; kc < 4; kc++) {
            uint4 a = af_s[kc * 32 + lane];
            uint32_t ar[4] = {a.x, a.y, a.z, a.w};
#pragma unroll
            for (int j = 0; j < 8; j++) {
                uint2 b = bf[j];
                if (kc < 3) bf[j] = __ldg(bb + (half * 8 + j) * 128 + (kc + 1) * 32);
                mma_f16acc(acc[half * 8 + j], ar, b.x, b.y);
            }
        }
    }

    // ---- pass 1: expand to fp32, qv = rcp(S), rowsum, row-min q ----
    float qv[16][4];
    float rs[2]   = {0.f, 0.f};
    float qmin[2] = {3.4e38f, 3.4e38f};
    const int wc0 = wid * 128;
    const float zn0 = zn2_s[g];
    const float zn1 = zn2_s[g + 8];

#pragma unroll
    for (int nt = 0; nt < 16; nt++) {
        float2 dlo = __half22float2(*(const __half2*)&acc[nt][0]); // row g
        float2 dhi = __half22float2(*(const __half2*)&acc[nt][1]); // row g+8
        int c0 = wc0 + nt * 8 + tq * 2;
        float w0 = wn_s[c0], w1 = wn_s[c0 + 1];
        float S00 = dlo.x + zn0 + w0, S01 = dlo.y + zn0 + w1;
        float S10 = dhi.x + zn1 + w0, S11 = dhi.y + zn1 + w1;
        float q00 = rcpf(S00), q01 = rcpf(S01);
        float q10 = rcpf(S10), q11 = rcpf(S11);
        qv[nt][0] = q00; qv[nt][1] = q01;
        qv[nt][2] = q10; qv[nt][3] = q11;
        rs[0] += q00 + q01;
        rs[1] += q10 + q11;
        qmin[0] = fminf(qmin[0], fminf(q00, q01));
        qmin[1] = fminf(qmin[1], fminf(q10, q11));
    }
#pragma unroll
    for (int m = 1; m <= 2; m <<= 1) {
#pragma unroll
        for (int h = 0; h < 2; h++) {
            rs[h]  += __shfl_xor_sync(0xFFFFFFFFu, rs[h], m);
            qmin[h] = fminf(qmin[h], __shfl_xor_sync(0xFFFFFFFFu, qmin[h], m));
        }
    }
    if (tq == 0) {
#pragma unroll
        for (int h = 0; h < 2; h++) {
            rs_p[wid][g + h * 8] = rs[h];
            qm_p[wid][g + h * 8] = qmin[h];
        }
    }
    __syncthreads();
    if (tid < 16) {
        float s = 0.f, qm = 3.4e38f;
#pragma unroll
        for (int w = 0; w < NWARP; w++) {
            s += rs_p[w][tid];
            qm = fminf(qm, qm_p[w][tid]);
        }
        inv_s[tid] = 1.0f / s;
        float Smax = 1.0f / qm;
        thr_s[tid] = 1.0f / (Smax - EPS);
    }
    __syncthreads();

    // ---- candidate scan ----
    {
        float thr0 = thr_s[g];
        float thr1 = thr_s[g + 8];
#pragma unroll
        for (int nt = 0; nt < 16; nt++) {
#pragma unroll
            for (int p = 0; p < 2; p++) {
                if (qv[nt][p] <= thr0) {
                    int c = wc0 + nt * 8 + tq * 2 + p;
                    int i = atomicAdd(&ncand_s, 1);
                    if (i < MAXCAND)
                        cand_s[i] = ((unsigned int)g << 16) | (unsigned int)c;
                }
                if (qv[nt][2 + p] <= thr1) {
                    int c = wc0 + nt * 8 + tq * 2 + p;
                    int i = atomicAdd(&ncand_s, 1);
                    if (i < MAXCAND)
                        cand_s[i] = ((unsigned int)(g + 8) << 16) | (unsigned int)c;
                }
            }
        }
    }
    __syncthreads();

    // ---- exact fp32 refine (one warp per candidate) ----
    {
        int nc = ncand_s < MAXCAND ? ncand_s : MAXCAND;
        for (int i = wid; i < nc; i += NWARP) {
            unsigned int pc = cand_s[i];
            int rr = pc >> 16, c = pc & 0xFFFF;
            float2 zv = ((const float2*)(z_s + rr * 64))[lane];
            float2 ev = __ldg((const float2*)(cb + (size_t)c * 64) + lane);
            float p = zv.x * ev.x + zv.y * ev.y;
#pragma unroll
            for (int m = 16; m > 0; m >>= 1)
                p += __shfl_xor_sync(0xFFFFFFFFu, p, m);
            if (lane == 0) {
                float d = zn2_s[rr] + (wn_s[c] - 1.0f) - 2.f * p;
                unsigned long long key =
                    ((unsigned long long)ordered_u32(d) << 32) |
                    (unsigned long long)(0xFFFFFFFFu - (unsigned int)c);
                atomicMax(&rowbest[rr], key);
            }
        }
    }
    __syncthreads();
    if (tid < 16)
        bc_s[tid] = (int)(0xFFFFFFFFu -
                          (unsigned int)(rowbest[tid] & 0xFFFFFFFFull));
    __syncthreads();

    // ---- store normalized q ----
    {
        float inv0 = inv_s[g];
        float inv1 = inv_s[g + 8];
        float* base0 = q_out + (size_t)(r0 + g) * 1024 + wc0 + tq * 2;
        float* base1 = q_out + (size_t)(r0 + g + 8) * 1024 + wc0 + tq * 2;
#pragma unroll
        for (int nt = 0; nt < 16; nt++) {
            float2 v0, v1;
            v0.x = qv[nt][0] * inv0; v0.y = qv[nt][1] * inv0;
            v1.x = qv[nt][2] * inv1; v1.y = qv[nt][3] * inv1;
            *(float2*)(base0 + nt * 8) = v0;
            *(float2*)(base1 + nt * 8) = v1;
        }
    }

    // ---- gather z_q, store, loss ----
    float lp;
    {
        int rr = tid >> 4, j4 = tid & 15;
        int cbest = bc_s[rr];
        float4 e  = ((const float4*)(cb + (size_t)cbest * 64))[j4];
        float4 zv = ((const float4*)z_s)[rr * 16 + j4];
        ((float4*)(zq_out + (size_t)(r0 + rr) * 64))[j4] = e;
        float dx = e.x - zv.x, dy = e.y - zv.y,
              dz = e.z - zv.z, dw = e.w - zv.w;
        lp = dx * dx + dy * dy + dz * dz + dw * dw;
    }
#pragma unroll
    for (int m = 16; m > 0; m >>= 1)
        lp += __shfl_xor_sync(0xFFFFFFFFu, lp, m);
    float* red = &rs_p[0][0];
    if (lane == 0) red[wid] = lp;
    __syncthreads();
    if (tid < 8) {
        float v = red[tid];
#pragma unroll
        for (int m = 4; m > 0; m >>= 1)
            v += __shfl_xor_sync(0x000000FFu, v, m);
        if (tid == 0) atomicAdd(&g_loss, (double)v);
    }
}

__global__ void vq_finalize(float* __restrict__ loss_out) {
    loss_out[0] = (float)(1.25 * g_loss / (65536.0 * 64.0));
}

extern "C" void kernel_launch(void* const* d_in, const int* in_sizes, int n_in,
                              void* d_out, int out_size) {
    (void)in_sizes; (void)n_in; (void)out_size;
    const float* z  = (const float*)d_in[0];
    const float* cb = (const float*)d_in[1];
    float* out      = (float*)d_out;
    float* q_out    = out;
    float* zq_out   = out + (size_t)65536 * 1024;
    float* loss_out = zq_out + (size_t)65536 * 64;

    vq_prep<<<128, 256>>>(cb);
    vq_main<<<65536 / BM, THREADS>>>(z, cb, q_out, zq_out);
    vq_finalize<<<1, 1>>>(loss_out);
}

// round 9
// speedup vs baseline: 1.0110x; 1.0110x over previous
#include <cuda_runtime.h>
#include <cuda_fp16.h>
#include <cstdint>

#define THREADS 256
#define NWARP   8
#define EPS     0.10f
#define MAXCAND 256

__device__ uint4  g_bfrag4[128 * 2 * 32];  // [ntg][kpair][lane] fp16 frags of -2e
__device__ float  g_wn1[1024];             // ||e_c||^2 + 1
__device__ double g_loss;
__device__ unsigned int g_done = 0;

__device__ __forceinline__ float rcpf(float x) {
    float r; asm("rcp.approx.f32 %0, %1;" : "=f"(r) : "f"(x)); return r;
}
__device__ __forceinline__ unsigned int ordered_u32(float f) {
    unsigned int u = __float_as_uint(f);
    return (u & 0x80000000u) ? ~u : (u | 0x80000000u);
}
__device__ __forceinline__ void mma_fp16(float* d, const uint32_t* a,
                                         uint32_t b0, uint32_t b1) {
    asm volatile(
        "mma.sync.aligned.m16n8k16.row.col.f32.f16.f16.f32 "
        "{%0,%1,%2,%3}, {%4,%5,%6,%7}, {%8,%9}, {%0,%1,%2,%3};"
        : "+f"(d[0]), "+f"(d[1]), "+f"(d[2]), "+f"(d[3])
        : "r"(a[0]), "r"(a[1]), "r"(a[2]), "r"(a[3]), "r"(b0), "r"(b1));
}
__device__ __forceinline__ uint32_t h2pack(float a, float b) {
    __half2 h = __floats2half2_rn(a, b);
    return *(uint32_t*)&h;
}

// ---------------------------------------------------------------------------
// Prep: block ntg stages 8 codebook rows -> wn1 + fp16 B fragments (uint4)
// ---------------------------------------------------------------------------
__global__ void vq_prep(const float* __restrict__ cb) {
    __shared__ float rows[8 * 64];
    const int tid = threadIdx.x;
    const int ntg = blockIdx.x;
    if (ntg == 0 && tid == 0) g_loss = 0.0;
    ((float4*)rows)[tid] = ((const float4*)(cb + (size_t)ntg * 512))[tid];
    __syncthreads();
    if (tid < 8) {
        float s = 0.f;
        const float* r = rows + tid * 64;
#pragma unroll 16
        for (int k = 0; k < 64; k++) { float v = r[k]; s += v * v; }
        g_wn1[ntg * 8 + tid] = s + 1.f;
    }
    if (tid < 64) {
        const int lane = tid & 31;
        const int kp   = tid >> 5;           // kpair 0..1 (kc = 2kp, 2kp+1)
        const int g = lane >> 2, tq = lane & 3;
        const float* r = rows + g * 64;
        int ka = (2 * kp) * 16 + tq * 2;
        int kb = (2 * kp + 1) * 16 + tq * 2;
        uint4 v;
        v.x = h2pack(-2.f * r[ka],     -2.f * r[ka + 1]);
        v.y = h2pack(-2.f * r[ka + 8], -2.f * r[ka + 9]);
        v.z = h2pack(-2.f * r[kb],     -2.f * r[kb + 1]);
        v.w = h2pack(-2.f * r[kb + 8], -2.f * r[kb + 9]);
        g_bfrag4[(size_t)ntg * 64 + kp * 32 + lane] = v;
    }
}

// ---------------------------------------------------------------------------
// Main: 2 tiles of (16 rows x 1024 cols) per CTA, 8 warps, occ 2/SM
// ---------------------------------------------------------------------------
__global__ void __launch_bounds__(THREADS, 2)
vq_main(const float* __restrict__ z, const float* __restrict__ cb,
        float* __restrict__ q_out, float* __restrict__ zq_out,
        float* __restrict__ loss_out, int ncta) {
    __shared__ float z_s[16 * 64];
    __shared__ uint4 af_s[128];               // A frags [kc][lane]
    __shared__ float wn_s[1024];
    __shared__ float zn2_s[16];
    __shared__ float inv_s[16];
    __shared__ float thr_s[16];
    __shared__ int   bc_s[16];
    __shared__ float rs_p[NWARP][16];
    __shared__ float qm_p[NWARP][16];
    __shared__ unsigned long long rowbest[16];
    __shared__ unsigned int cand_s[MAXCAND];
    __shared__ int ncand_s;

    const int tid  = threadIdx.x;
    const int wid  = tid >> 5;
    const int lane = tid & 31;
    const int g    = lane >> 2;
    const int tq   = lane & 3;

    ((float4*)wn_s)[tid] = ((const float4*)g_wn1)[tid];

    // prefetch z tile 0
    float4 zpre = __ldg(((const float4*)(z + (size_t)blockIdx.x * 32 * 64)) + tid);
    float lp_total = 0.f;

#pragma unroll 1
    for (int tile = 0; tile < 2; tile++) {
        const int r0 = blockIdx.x * 32 + tile * 16;
        __syncthreads();                 // prior tile readers of z_s done
        ((float4*)z_s)[tid] = zpre;
        if (tile == 0)                   // prefetch tile 1 (hidden by tile-0 work)
            zpre = __ldg(((const float4*)(z + ((size_t)blockIdx.x * 32 + 16) * 64)) + tid);
        __syncthreads();

        // A fragments fp16: slot = kc*32 + lane
        if (tid < 128) {
            int kc = tid >> 5, ln = tid & 31;
            int gg = ln >> 2, qq = ln & 3;
            int k0 = kc * 16 + qq * 2;
            const float* zr0 = z_s + gg * 64;
            const float* zr1 = z_s + (gg + 8) * 64;
            uint4 v;
            v.x = h2pack(zr0[k0],     zr0[k0 + 1]);
            v.y = h2pack(zr1[k0],     zr1[k0 + 1]);
            v.z = h2pack(zr0[k0 + 8], zr0[k0 + 9]);
            v.w = h2pack(zr1[k0 + 8], zr1[k0 + 9]);
            af_s[tid] = v;
        }
        if (tid < 16) {
            float s = 0.f;
            const float* zr = z_s + tid * 64;
#pragma unroll 16
            for (int k = 0; k < 64; k++) { float v = zr[k]; s += v * v; }
            zn2_s[tid] = s;
            rowbest[tid] = 0ull;
        }
        if (tid == 0) ncand_s = 0;
        __syncthreads();

        // ---- GEMM: warp wid owns cols wid*128..+127; 64 MMAs, 32 LDG.128 ----
        float acc[16][4];
#pragma unroll
        for (int nt = 0; nt < 16; nt++)
#pragma unroll
            for (int r = 0; r < 4; r++) acc[nt][r] = 0.f;

        const uint4* bb = g_bfrag4 + (size_t)(wid * 16) * 64 + lane;

#pragma unroll
        for (int half = 0; half < 2; half++) {
            uint4 bf[8];
#pragma unroll
            for (int j = 0; j < 8; j++)
                bf[j] = __ldg(bb + (half * 8 + j) * 64);
#pragma unroll
            for (int kp = 0; kp < 2; kp++) {
                uint4 a0 = af_s[(kp * 2 + 0) * 32 + lane];
                uint4 a1 = af_s[(kp * 2 + 1) * 32 + lane];
                uint32_t ar0[4] = {a0.x, a0.y, a0.z, a0.w};
                uint32_t ar1[4] = {a1.x, a1.y, a1.z, a1.w};
#pragma unroll
                for (int j = 0; j < 8; j++) {
                    uint4 b = bf[j];
                    if (kp == 0) bf[j] = __ldg(bb + (half * 8 + j) * 64 + 32);
                    mma_fp16(acc[half * 8 + j], ar0, b.x, b.y);
                    mma_fp16(acc[half * 8 + j], ar1, b.z, b.w);
                }
            }
        }

        // ---- pass 1: qv = rcp(S) in-place, rowsum, row-min q ----
        float rs[2]   = {0.f, 0.f};
        float qmin[2] = {3.4e38f, 3.4e38f};
        const int wc0 = wid * 128;
        const float zn0 = zn2_s[g];
        const float zn1 = zn2_s[g + 8];

#pragma unroll
        for (int nt = 0; nt < 16; nt++) {
            int c0 = wc0 + nt * 8 + tq * 2;
            float w0 = wn_s[c0], w1 = wn_s[c0 + 1];
            float q00 = rcpf(acc[nt][0] + zn0 + w0);
            float q01 = rcpf(acc[nt][1] + zn0 + w1);
            float q10 = rcpf(acc[nt][2] + zn1 + w0);
            float q11 = rcpf(acc[nt][3] + zn1 + w1);
            acc[nt][0] = q00; acc[nt][1] = q01;
            acc[nt][2] = q10; acc[nt][3] = q11;
            rs[0] += q00 + q01;
            rs[1] += q10 + q11;
            qmin[0] = fminf(qmin[0], fminf(q00, q01));
            qmin[1] = fminf(qmin[1], fminf(q10, q11));
        }
#pragma unroll
        for (int m = 1; m <= 2; m <<= 1) {
#pragma unroll
            for (int h = 0; h < 2; h++) {
                rs[h]  += __shfl_xor_sync(0xFFFFFFFFu, rs[h], m);
                qmin[h] = fminf(qmin[h], __shfl_xor_sync(0xFFFFFFFFu, qmin[h], m));
            }
        }
        if (tq == 0) {
#pragma unroll
            for (int h = 0; h < 2; h++) {
                rs_p[wid][g + h * 8] = rs[h];
                qm_p[wid][g + h * 8] = qmin[h];
            }
        }
        __syncthreads();
        if (tid < 16) {
            float s = 0.f, qm = 3.4e38f;
#pragma unroll
            for (int w = 0; w < NWARP; w++) {
                s += rs_p[w][tid];
                qm = fminf(qm, qm_p[w][tid]);
            }
            inv_s[tid] = 1.0f / s;
            float Smax = 1.0f / qm;
            thr_s[tid] = 1.0f / (Smax - EPS);
        }
        __syncthreads();

        // ---- store normalized q early (STG drain overlaps scan/refine) ----
        {
            float inv0 = inv_s[g];
            float inv1 = inv_s[g + 8];
            float* base0 = q_out + (size_t)(r0 + g) * 1024 + wc0 + tq * 2;
            float* base1 = q_out + (size_t)(r0 + g + 8) * 1024 + wc0 + tq * 2;
#pragma unroll
            for (int nt = 0; nt < 16; nt++) {
                float2 v0, v1;
                v0.x = acc[nt][0] * inv0; v0.y = acc[nt][1] * inv0;
                v1.x = acc[nt][2] * inv1; v1.y = acc[nt][3] * inv1;
                *(float2*)(base0 + nt * 8) = v0;
                *(float2*)(base1 + nt * 8) = v1;
            }
        }

        // ---- candidate scan ----
        {
            float thr0 = thr_s[g];
            float thr1 = thr_s[g + 8];
#pragma unroll
            for (int nt = 0; nt < 16; nt++) {
#pragma unroll
                for (int p = 0; p < 2; p++) {
                    if (acc[nt][p] <= thr0) {
                        int c = wc0 + nt * 8 + tq * 2 + p;
                        int i = atomicAdd(&ncand_s, 1);
                        if (i < MAXCAND)
                            cand_s[i] = ((unsigned int)g << 16) | (unsigned int)c;
                    }
                    if (acc[nt][2 + p] <= thr1) {
                        int c = wc0 + nt * 8 + tq * 2 + p;
                        int i = atomicAdd(&ncand_s, 1);
                        if (i < MAXCAND)
                            cand_s[i] = ((unsigned int)(g + 8) << 16) | (unsigned int)c;
                    }
                }
            }
        }
        __syncthreads();

        // ---- exact fp32 refine (one warp per candidate) ----
        {
            int nc = ncand_s < MAXCAND ? ncand_s : MAXCAND;
            for (int i = wid; i < nc; i += NWARP) {
                unsigned int pc = cand_s[i];
                int rr = pc >> 16, c = pc & 0xFFFF;
                float2 zv = ((const float2*)(z_s + rr * 64))[lane];
                float2 ev = __ldg((const float2*)(cb + (size_t)c * 64) + lane);
                float p = zv.x * ev.x + zv.y * ev.y;
#pragma unroll
                for (int m = 16; m > 0; m >>= 1)
                    p += __shfl_xor_sync(0xFFFFFFFFu, p, m);
                if (lane == 0) {
                    float d = zn2_s[rr] + (wn_s[c] - 1.0f) - 2.f * p;
                    unsigned long long key =
                        ((unsigned long long)ordered_u32(d) << 32) |
                        (unsigned long long)(0xFFFFFFFFu - (unsigned int)c);
                    atomicMax(&rowbest[rr], key);
                }
            }
        }
        __syncthreads();
        if (tid < 16)
            bc_s[tid] = (int)(0xFFFFFFFFu -
                              (unsigned int)(rowbest[tid] & 0xFFFFFFFFull));
        __syncthreads();

        // ---- gather z_q, store, loss partial ----
        {
            int rr = tid >> 4, j4 = tid & 15;
            int cbest = bc_s[rr];
            float4 e  = ((const float4*)(cb + (size_t)cbest * 64))[j4];
            float4 zv = ((const float4*)z_s)[rr * 16 + j4];
            ((float4*)(zq_out + (size_t)(r0 + rr) * 64))[j4] = e;
            float dx = e.x - zv.x, dy = e.y - zv.y,
                  dz = e.z - zv.z, dw = e.w - zv.w;
            lp_total += dx * dx + dy * dy + dz * dz + dw * dw;
        }
    }

    // ---- loss reduce + completion-counter finalize ----
#pragma unroll
    for (int m = 16; m > 0; m >>= 1)
        lp_total += __shfl_xor_sync(0xFFFFFFFFu, lp_total, m);
    float* red = &rs_p[0][0];
    if (lane == 0) red[wid] = lp_total;
    __syncthreads();
    if (tid == 0) {
        float v = 0.f;
#pragma unroll
        for (int w = 0; w < NWARP; w++) v += red[w];
        atomicAdd(&g_loss, (double)v);
        __threadfence();
        unsigned int old = atomicAdd(&g_done, 1u);
        if (old == (unsigned int)(ncta - 1)) {
            __threadfence();
            loss_out[0] = (float)(1.25 * g_loss / (65536.0 * 64.0));
            g_done = 0;
        }
    }
}

extern "C" void kernel_launch(void* const* d_in, const int* in_sizes, int n_in,
                              void* d_out, int out_size) {
    (void)in_sizes; (void)n_in; (void)out_size;
    const float* z  = (const float*)d_in[0];
    const float* cb = (const float*)d_in[1];
    float* out      = (float*)d_out;
    float* q_out    = out;
    float* zq_out   = out + (size_t)65536 * 1024;
    float* loss_out = zq_out + (size_t)65536 * 64;

    vq_prep<<<128, 128>>>(cb);
    vq_main<<<2048, THREADS>>>(z, cb, q_out, zq_out, loss_out, 2048);
}

// round 10
// speedup vs baseline: 1.0662x; 1.0546x over previous
#include <cuda_runtime.h>
#include <cuda_fp16.h>
#include <cstdint>

#define THREADS 256
#define NWARP   8
#define EPS     0.10f
#define MAXCAND 256

__device__ uint4  g_bfrag4[128 * 2 * 32];  // [ntg][kpair][lane] fp16 frags of -2e
__device__ float  g_wn1[1024];             // ||e_c||^2 + 1
__device__ double g_loss;
__device__ unsigned int g_done = 0;

__device__ __forceinline__ float rcpf(float x) {
    float r; asm("rcp.approx.f32 %0, %1;" : "=f"(r) : "f"(x)); return r;
}
__device__ __forceinline__ unsigned int ordered_u32(float f) {
    unsigned int u = __float_as_uint(f);
    return (u & 0x80000000u) ? ~u : (u | 0x80000000u);
}
// fp16-accumulate MMA: C/D fp16 (2 regs) — halves accumulator registers
__device__ __forceinline__ void mma_f16acc(uint32_t* c, const uint32_t* a,
                                           uint32_t b0, uint32_t b1) {
    asm volatile(
        "mma.sync.aligned.m16n8k16.row.col.f16.f16.f16.f16 "
        "{%0,%1}, {%2,%3,%4,%5}, {%6,%7}, {%0,%1};"
        : "+r"(c[0]), "+r"(c[1])
        : "r"(a[0]), "r"(a[1]), "r"(a[2]), "r"(a[3]), "r"(b0), "r"(b1));
}
__device__ __forceinline__ uint32_t h2pack(float a, float b) {
    __half2 h = __floats2half2_rn(a, b);
    return *(uint32_t*)&h;
}

// ---------------------------------------------------------------------------
// Prep: block ntg stages 8 codebook rows -> wn1 + fp16 B fragments (uint4)
// ---------------------------------------------------------------------------
__global__ void vq_prep(const float* __restrict__ cb) {
    __shared__ float rows[8 * 64];
    const int tid = threadIdx.x;
    const int ntg = blockIdx.x;
    if (ntg == 0 && tid == 0) g_loss = 0.0;
    ((float4*)rows)[tid] = ((const float4*)(cb + (size_t)ntg * 512))[tid];
    __syncthreads();
    if (tid < 8) {
        float s = 0.f;
        const float* r = rows + tid * 64;
#pragma unroll 16
        for (int k = 0; k < 64; k++) { float v = r[k]; s += v * v; }
        g_wn1[ntg * 8 + tid] = s + 1.f;
    }
    if (tid < 64) {
        const int lane = tid & 31;
        const int kp   = tid >> 5;
        const int g = lane >> 2, tq = lane & 3;
        const float* r = rows + g * 64;
        int ka = (2 * kp) * 16 + tq * 2;
        int kb = (2 * kp + 1) * 16 + tq * 2;
        uint4 v;
        v.x = h2pack(-2.f * r[ka],     -2.f * r[ka + 1]);
        v.y = h2pack(-2.f * r[ka + 8], -2.f * r[ka + 9]);
        v.z = h2pack(-2.f * r[kb],     -2.f * r[kb + 1]);
        v.w = h2pack(-2.f * r[kb + 8], -2.f * r[kb + 9]);
        g_bfrag4[(size_t)ntg * 64 + kp * 32 + lane] = v;
    }
}

// ---------------------------------------------------------------------------
// Main: 2 tiles of (16 rows x 1024 cols) per CTA, 8 warps, target occ 3/SM
// ---------------------------------------------------------------------------
__global__ void __launch_bounds__(THREADS, 3)
vq_main(const float* __restrict__ z, const float* __restrict__ cb,
        float* __restrict__ q_out, float* __restrict__ zq_out,
        float* __restrict__ loss_out, int ncta) {
    __shared__ float z_s[16 * 64];
    __shared__ uint4 af_s[128];               // A frags [kc][lane]
    __shared__ float wn_s[1024];
    __shared__ float zn2_s[16];
    __shared__ float inv_s[16];
    __shared__ float thr_s[16];
    __shared__ int   bc_s[16];
    __shared__ float rs_p[NWARP][16];
    __shared__ float qm_p[NWARP][16];
    __shared__ unsigned long long rowbest[16];
    __shared__ unsigned int cand_s[MAXCAND];
    __shared__ int ncand_s;

    const int tid  = threadIdx.x;
    const int wid  = tid >> 5;
    const int lane = tid & 31;
    const int g    = lane >> 2;
    const int tq   = lane & 3;

    ((float4*)wn_s)[tid] = ((const float4*)g_wn1)[tid];

    float4 zpre = __ldg(((const float4*)(z + (size_t)blockIdx.x * 32 * 64)) + tid);
    float lp_total = 0.f;

#pragma unroll 1
    for (int tile = 0; tile < 2; tile++) {
        const int r0 = blockIdx.x * 32 + tile * 16;
        __syncthreads();
        ((float4*)z_s)[tid] = zpre;
        if (tile == 0)
            zpre = __ldg(((const float4*)(z + ((size_t)blockIdx.x * 32 + 16) * 64)) + tid);
        __syncthreads();

        if (tid < 128) {
            int kc = tid >> 5, ln = tid & 31;
            int gg = ln >> 2, qq = ln & 3;
            int k0 = kc * 16 + qq * 2;
            const float* zr0 = z_s + gg * 64;
            const float* zr1 = z_s + (gg + 8) * 64;
            uint4 v;
            v.x = h2pack(zr0[k0],     zr0[k0 + 1]);
            v.y = h2pack(zr1[k0],     zr1[k0 + 1]);
            v.z = h2pack(zr0[k0 + 8], zr0[k0 + 9]);
            v.w = h2pack(zr1[k0 + 8], zr1[k0 + 9]);
            af_s[tid] = v;
        }
        if (tid < 16) {
            float s = 0.f;
            const float* zr = z_s + tid * 64;
#pragma unroll 16
            for (int k = 0; k < 64; k++) { float v = zr[k]; s += v * v; }
            zn2_s[tid] = s;
            rowbest[tid] = 0ull;
        }
        if (tid == 0) ncand_s = 0;
        __syncthreads();

        // ---- GEMM (f16 acc): warp owns cols wid*128..+127; 64 MMAs ----
        uint32_t acc[16][2];
#pragma unroll
        for (int nt = 0; nt < 16; nt++) { acc[nt][0] = 0u; acc[nt][1] = 0u; }

        const uint4* bb = g_bfrag4 + (size_t)(wid * 16) * 64 + lane;

#pragma unroll
        for (int grp = 0; grp < 4; grp++) {
            uint4 bf[4];
#pragma unroll
            for (int j = 0; j < 4; j++)
                bf[j] = __ldg(bb + (grp * 4 + j) * 64);
#pragma unroll
            for (int kp = 0; kp < 2; kp++) {
                uint4 a0 = af_s[(kp * 2 + 0) * 32 + lane];
                uint4 a1 = af_s[(kp * 2 + 1) * 32 + lane];
                uint32_t ar0[4] = {a0.x, a0.y, a0.z, a0.w};
                uint32_t ar1[4] = {a1.x, a1.y, a1.z, a1.w};
#pragma unroll
                for (int j = 0; j < 4; j++) {
                    uint4 b = bf[j];
                    if (kp == 0) bf[j] = __ldg(bb + (grp * 4 + j) * 64 + 32);
                    mma_f16acc(acc[grp * 4 + j], ar0, b.x, b.y);
                    mma_f16acc(acc[grp * 4 + j], ar1, b.z, b.w);
                }
            }
        }

        // ---- pass A: rowsum + row-min q (qv recomputed later, not stored) ----
        float rs[2]   = {0.f, 0.f};
        float qmin[2] = {3.4e38f, 3.4e38f};
        const int wc0 = wid * 128;
        const float zn0 = zn2_s[g];
        const float zn1 = zn2_s[g + 8];

#pragma unroll
        for (int nt = 0; nt < 16; nt++) {
            float2 dlo = __half22float2(*(const __half2*)&acc[nt][0]);
            float2 dhi = __half22float2(*(const __half2*)&acc[nt][1]);
            int c0 = wc0 + nt * 8 + tq * 2;
            float w0 = wn_s[c0], w1 = wn_s[c0 + 1];
            float q00 = rcpf(dlo.x + zn0 + w0);
            float q01 = rcpf(dlo.y + zn0 + w1);
            float q10 = rcpf(dhi.x + zn1 + w0);
            float q11 = rcpf(dhi.y + zn1 + w1);
            rs[0] += q00 + q01;
            rs[1] += q10 + q11;
            qmin[0] = fminf(qmin[0], fminf(q00, q01));
            qmin[1] = fminf(qmin[1], fminf(q10, q11));
        }
#pragma unroll
        for (int m = 1; m <= 2; m <<= 1) {
#pragma unroll
            for (int h = 0; h < 2; h++) {
                rs[h]  += __shfl_xor_sync(0xFFFFFFFFu, rs[h], m);
                qmin[h] = fminf(qmin[h], __shfl_xor_sync(0xFFFFFFFFu, qmin[h], m));
            }
        }
        if (tq == 0) {
#pragma unroll
            for (int h = 0; h < 2; h++) {
                rs_p[wid][g + h * 8] = rs[h];
                qm_p[wid][g + h * 8] = qmin[h];
            }
        }
        __syncthreads();
        if (tid < 16) {
            float s = 0.f, qm = 3.4e38f;
#pragma unroll
            for (int w = 0; w < NWARP; w++) {
                s += rs_p[w][tid];
                qm = fminf(qm, qm_p[w][tid]);
            }
            inv_s[tid] = 1.0f / s;
            float Smax = 1.0f / qm;
            thr_s[tid] = 1.0f / (Smax - EPS);
        }
        __syncthreads();

        // ---- pass B: recompute qv, store normalized q, candidate scan ----
        {
            float inv0 = inv_s[g],  inv1 = inv_s[g + 8];
            float thr0 = thr_s[g],  thr1 = thr_s[g + 8];
            float* base0 = q_out + (size_t)(r0 + g) * 1024 + wc0 + tq * 2;
            float* base1 = q_out + (size_t)(r0 + g + 8) * 1024 + wc0 + tq * 2;
#pragma unroll
            for (int nt = 0; nt < 16; nt++) {
                float2 dlo = __half22float2(*(const __half2*)&acc[nt][0]);
                float2 dhi = __half22float2(*(const __half2*)&acc[nt][1]);
                int c0 = wc0 + nt * 8 + tq * 2;
                float w0 = wn_s[c0], w1 = wn_s[c0 + 1];
                float q00 = rcpf(dlo.x + zn0 + w0);
                float q01 = rcpf(dlo.y + zn0 + w1);
                float q10 = rcpf(dhi.x + zn1 + w0);
                float q11 = rcpf(dhi.y + zn1 + w1);
                float2 v0, v1;
                v0.x = q00 * inv0; v0.y = q01 * inv0;
                v1.x = q10 * inv1; v1.y = q11 * inv1;
                *(float2*)(base0 + nt * 8) = v0;
                *(float2*)(base1 + nt * 8) = v1;
                if (q00 <= thr0 || q01 <= thr0) {
                    if (q00 <= thr0) {
                        int i = atomicAdd(&ncand_s, 1);
                        if (i < MAXCAND)
                            cand_s[i] = ((unsigned int)g << 16) | (unsigned int)c0;
                    }
                    if (q01 <= thr0) {
                        int i = atomicAdd(&ncand_s, 1);
                        if (i < MAXCAND)
                            cand_s[i] = ((unsigned int)g << 16) | (unsigned int)(c0 + 1);
                    }
                }
                if (q10 <= thr1 || q11 <= thr1) {
                    if (q10 <= thr1) {
                        int i = atomicAdd(&ncand_s, 1);
                        if (i < MAXCAND)
                            cand_s[i] = ((unsigned int)(g + 8) << 16) | (unsigned int)c0;
                    }
                    if (q11 <= thr1) {
                        int i = atomicAdd(&ncand_s, 1);
                        if (i < MAXCAND)
                            cand_s[i] = ((unsigned int)(g + 8) << 16) | (unsigned int)(c0 + 1);
                    }
                }
            }
        }
        __syncthreads();

        // ---- exact fp32 refine (one warp per candidate) ----
        {
            int nc = ncand_s < MAXCAND ? ncand_s : MAXCAND;
            for (int i = wid; i < nc; i += NWARP) {
                unsigned int pc = cand_s[i];
                int rr = pc >> 16, c = pc & 0xFFFF;
                float2 zv = ((const float2*)(z_s + rr * 64))[lane];
                float2 ev = __ldg((const float2*)(cb + (size_t)c * 64) + lane);
                float p = zv.x * ev.x + zv.y * ev.y;
#pragma unroll
                for (int m = 16; m > 0; m >>= 1)
                    p += __shfl_xor_sync(0xFFFFFFFFu, p, m);
                if (lane == 0) {
                    float d = zn2_s[rr] + (wn_s[c] - 1.0f) - 2.f * p;
                    unsigned long long key =
                        ((unsigned long long)ordered_u32(d) << 32) |
                        (unsigned long long)(0xFFFFFFFFu - (unsigned int)c);
                    atomicMax(&rowbest[rr], key);
                }
            }
        }
        __syncthreads();
        if (tid < 16)
            bc_s[tid] = (int)(0xFFFFFFFFu -
                              (unsigned int)(rowbest[tid] & 0xFFFFFFFFull));
        __syncthreads();

        // ---- gather z_q, store, loss partial ----
        {
            int rr = tid >> 4, j4 = tid & 15;
            int cbest = bc_s[rr];
            float4 e  = ((const float4*)(cb + (size_t)cbest * 64))[j4];
            float4 zv = ((const float4*)z_s)[rr * 16 + j4];
            ((float4*)(zq_out + (size_t)(r0 + rr) * 64))[j4] = e;
            float dx = e.x - zv.x, dy = e.y - zv.y,
                  dz = e.z - zv.z, dw = e.w - zv.w;
            lp_total += dx * dx + dy * dy + dz * dz + dw * dw;
        }
    }

    // ---- loss reduce + completion-counter finalize ----
#pragma unroll
    for (int m = 16; m > 0; m >>= 1)
        lp_total += __shfl_xor_sync(0xFFFFFFFFu, lp_total, m);
    float* red = &rs_p[0][0];
    if (lane == 0) red[wid] = lp_total;
    __syncthreads();
    if (tid == 0) {
        float v = 0.f;
#pragma unroll
        for (int w = 0; w < NWARP; w++) v += red[w];
        atomicAdd(&g_loss, (double)v);
        __threadfence();
        unsigned int old = atomicAdd(&g_done, 1u);
        if (old == (unsigned int)(ncta - 1)) {
            __threadfence();
            loss_out[0] = (float)(1.25 * g_loss / (65536.0 * 64.0));
            g_done = 0;
        }
    }
}

extern "C" void kernel_launch(void* const* d_in, const int* in_sizes, int n_in,
                              void* d_out, int out_size) {
    (void)in_sizes; (void)n_in; (void)out_size;
    const float* z  = (const float*)d_in[0];
    const float* cb = (const float*)d_in[1];
    float* out      = (float*)d_out;
    float* q_out    = out;
    float* zq_out   = out + (size_t)65536 * 1024;
    float* loss_out = zq_out + (size_t)65536 * 64;

    vq_prep<<<128, 128>>>(cb);
    vq_main<<<2048, THREADS>>>(z, cb, q_out, zq_out, loss_out, 2048);
}